// round 11
// baseline (speedup 1.0000x reference)
#include <cuda_runtime.h>
#include <cuda_bf16.h>
#include <cstdint>

typedef unsigned long long ull;

#define CDIM 256
#define VDIM 25
#define NSAMP 4
#define PE_LEN 89
#define NEG_SLOPE 0.01f
#define NTHR 1024

// ---- SMEM offsets from 1024-aligned base ----
#define H_OFF    0u          // 128 rows x 1024 B (Hh k<256 | Hl k>=256), also D
#define W_OFF    131072u     // 2 x 32 KB W chunk buffers
#define WBUF     32768u
#define AS2_OFF  196608u     // 25 x 13 packed f32x2 A rows = 2600 B
#define BIAS_OFF 199232u     // 3 x 256 f32
#define SMEM_DYN 203328u

// ---------------------------------------------------------------------------
// helpers
// ---------------------------------------------------------------------------
__device__ __forceinline__ uint32_t smem_u32(const void* p) {
    uint32_t a;
    asm("{ .reg .u64 t; cvta.to.shared.u64 t, %1; cvt.u32.u64 %0, t; }"
        : "=r"(a) : "l"(p));
    return a;
}
__device__ __forceinline__ ull fma2(ull a, ull b, ull c) {
    ull d;
    asm("fma.rn.f32x2 %0, %1, %2, %3;" : "=l"(d) : "l"(a), "l"(b), "l"(c));
    return d;
}
__device__ __forceinline__ void cpasync16(uint32_t dst, const void* src) {
    asm volatile("cp.async.cg.shared.global [%0], [%1], 16;" :: "r"(dst), "l"(src));
}
#define CP_COMMIT() asm volatile("cp.async.commit_group;" ::: "memory")
#define CP_WAIT1()  asm volatile("cp.async.wait_group 1;" ::: "memory")
#define CP_WAIT0()  asm volatile("cp.async.wait_group 0;" ::: "memory")

__device__ __forceinline__ void ldsm4(uint32_t* r, uint32_t a) {
    asm volatile("ldmatrix.sync.aligned.m8n8.x4.shared.b16 {%0,%1,%2,%3}, [%4];"
        : "=r"(r[0]), "=r"(r[1]), "=r"(r[2]), "=r"(r[3]) : "r"(a));
}
__device__ __forceinline__ void mma_bf16(float* d, const uint32_t* a,
                                         const uint32_t* b) {
    asm volatile(
        "mma.sync.aligned.m16n8k16.row.col.f32.bf16.bf16.f32 "
        "{%0,%1,%2,%3}, {%4,%5,%6,%7}, {%8,%9}, {%0,%1,%2,%3};"
        : "+f"(d[0]), "+f"(d[1]), "+f"(d[2]), "+f"(d[3])
        : "r"(a[0]), "r"(a[1]), "r"(a[2]), "r"(a[3]), "r"(b[0]), "r"(b[1]));
}
__device__ __forceinline__ void sts_f32(uint32_t a, float v) {
    asm volatile("st.shared.f32 [%0], %1;" :: "r"(a), "f"(v));
}
__device__ __forceinline__ float lds_f32(uint32_t a) {
    float v; asm volatile("ld.shared.f32 %0, [%1];" : "=f"(v) : "r"(a)); return v;
}
__device__ __forceinline__ void sts_u16(uint32_t a, uint16_t v) {
    asm volatile("st.shared.u16 [%0], %1;" :: "r"(a), "h"(v));
}
__device__ __forceinline__ ull lds_u64(uint32_t a) {
    ull v; asm volatile("ld.shared.b64 %0, [%1];" : "=l"(v) : "r"(a)); return v;
}
__device__ __forceinline__ void sts_u64(uint32_t a, ull v) {
    asm volatile("st.shared.b64 [%0], %1;" :: "r"(a), "l"(v));
}
__device__ __forceinline__ void sts_z16(uint32_t a) {
    asm volatile("st.shared.v4.b32 [%0], {%1,%1,%1,%1};" :: "r"(a), "r"(0u));
}

// H tile: [n row (0..127)] x [k (0..511)] bf16, 1024 B rows, XOR-swizzled
__device__ __forceinline__ uint32_t h_addr(uint32_t hb, int n, int k) {
    return hb + n * 1024 + ((((k >> 3) ^ (n & 7)) << 4) | ((k & 7) << 1));
}
// W chunk buffer: [o (0..255)] x [k (0..63)] bf16, 128 B rows, swizzled
__device__ __forceinline__ uint32_t w_addr(uint32_t wb, int o, int k) {
    return wb + o * 128 + ((((k >> 3) ^ (o & 7)) << 4) | ((k & 7) << 1));
}
// D (fp32) overlay in H region: [n][o], XOR-swizzled
__device__ __forceinline__ uint32_t d_addr(uint32_t hb, int n, int o) {
    return hb + n * 1024 + ((o ^ ((n & 7) << 2)) << 2);
}

__device__ __forceinline__ void split2(float v, uint16_t& hi, uint16_t& lo) {
    __nv_bfloat16 h = __float2bfloat16(v);
    __nv_bfloat16 l = __float2bfloat16(v - __bfloat162float(h));
    hi = __bfloat16_as_ushort(h);
    lo = __bfloat16_as_ushort(l);
}

// ---------------------------------------------------------------------------
// device globals + single merged prep kernel
// ---------------------------------------------------------------------------
__device__ float g_pe[PE_LEN * CDIM];
__device__ __nv_bfloat16 g_ws[3 * 2 * 256 * 256];   // [layer][part(hi/lo)][o][c]

#define PE_N   (PE_LEN * CDIM)
#define WS_N   (3 * CDIM * CDIM)

__global__ void prep_kernel(const float* __restrict__ w1,
                            const float* __restrict__ w2,
                            const float* __restrict__ wp) {
    int idx = blockIdx.x * blockDim.x + threadIdx.x;
    if (idx < PE_N) {
        int row = idx / CDIM, c = idx % CDIM;
        int p2 = (c >> 1) * 2;
        float divf = expf((float)p2 * (-9.210340371976184f / 256.0f));
        double ang = (double)row * (double)divf;
        g_pe[idx] = (c & 1) ? (float)cos(ang) : (float)sin(ang);
    } else if (idx < PE_N + WS_N) {
        int i = idx - PE_N;
        int l = i / (CDIM * CDIM), rem = i % (CDIM * CDIM);
        const float* w = (l == 0) ? w1 : ((l == 1) ? w2 : wp);
        float v = w[rem];
        __nv_bfloat16 h = __float2bfloat16(v);
        __nv_bfloat16 lo = __float2bfloat16(v - __bfloat162float(h));
        g_ws[((size_t)(l * 2 + 0) * 256) * 256 + rem] = h;
        g_ws[((size_t)(l * 2 + 1) * 256) * 256 + rem] = lo;
    }
}

// stage W virtual chunk vv (layer=vv>>3, part=vv&1, chunk=(vv>>1)&3) -> buf
__device__ __forceinline__ void stage_w(uint32_t wb, int vv, int tid) {
    const __nv_bfloat16* src = g_ws
        + ((size_t)((vv >> 3) * 2 + (vv & 1)) * 256) * 256
        + (size_t)(((vv >> 1) & 3) * 64);
#pragma unroll
    for (int q = 0; q < 2; q++) {
        int t = tid + q * NTHR;
        int o = t >> 3, k8 = (t & 7) << 3;
        cpasync16(w_addr(wb, o, k8), src + (size_t)o * 256 + k8);
    }
}

// ---------------------------------------------------------------------------
// main kernel: 1 CTA = 4 samples, 1024 threads (32 warps, 8x4 warp grid,
// warp tile 32x32 -> acc 32 regs; 64-reg/thread cap)
// ---------------------------------------------------------------------------
__global__ void __launch_bounds__(NTHR, 1)
ode_main(const float* __restrict__ x, const float* __restrict__ A,
         const float* __restrict__ b1, const float* __restrict__ b2,
         const float* __restrict__ bp, const int* __restrict__ tptr,
         float* __restrict__ out) {
    extern __shared__ char raw[];
    uint32_t rawu = smem_u32(raw);
    uint32_t base = (rawu + 1023u) & ~1023u;

    const int tid = threadIdx.x, lane = tid & 31, wid = tid >> 5;
    const int blk = blockIdx.x;
    const uint32_t hb = base + H_OFF;
    const int ob = (wid >> 2) * 32;     // warp m-tile origin (o), 8 tiles
    const int nb = (wid & 3) * 32;      // warp n-tile origin (rows), 4 tiles

    // kick off W prefetch for vchunks 0, 1 immediately
    stage_w(base + W_OFF, 0, tid);          CP_COMMIT();
    stage_w(base + W_OFF + WBUF, 1, tid);   CP_COMMIT();

    // stage A (packed f32x2 rows) + biases
    if (tid < VDIM * 13) {
        int i = tid;
        int v = i / 13, j = i % 13, u0 = 2 * j, u1 = 2 * j + 1;
        float f0 = A[v * VDIM + u0];
        float f1 = (u1 < VDIM) ? A[v * VDIM + u1] : 0.f;
        ull p = (ull)__float_as_uint(f0) | ((ull)__float_as_uint(f1) << 32);
        sts_u64(base + AS2_OFF + i * 8, p);
    }
    if (tid < 768) {
        float bv = (tid < 256) ? b1[tid]
                 : ((tid < 512) ? b2[tid - 256] : bp[tid - 512]);
        sts_f32(base + BIAS_OFF + tid * 4, bv);
    }

    // build H = split(x + pe): Hh at k=c, Hl at k=256+c; rows n = s*32+v
    const int t0 = *tptr;
    for (int i = tid; i < NSAMP * CDIM * VDIM; i += NTHR) {
        int s = i / (CDIM * VDIM);
        int rem = i - s * (CDIM * VDIM);
        int c = rem / VDIM, v = rem - c * VDIM;
        int n = blk * NSAMP + s;
        float val = x[(size_t)n * (CDIM * VDIM) + rem]
                  + g_pe[(t0 + (n & 63)) * CDIM + c];
        uint16_t hi, lo;
        split2(val, hi, lo);
        int nr = s * 32 + v;
        sts_u16(h_addr(hb, nr, c), hi);
        sts_u16(h_addr(hb, nr, 256 + c), lo);
    }
    // zero pad rows v=25..31 (28 rows x 1024 B)
    for (int i = tid; i < 28 * 64; i += NTHR) {
        int r = i >> 6;
        int s = r / 7, v = 25 + (r % 7);
        sts_z16(hb + (s * 32 + v) * 1024 + (i & 63) * 16);
    }
    __syncthreads();

    float acc[2][4][4];
#pragma unroll
    for (int i = 0; i < 2; i++)
#pragma unroll
        for (int j = 0; j < 4; j++)
#pragma unroll
            for (int e = 0; e < 4; e++) acc[i][j][e] = 0.f;

    // 24 virtual chunks: 3 layers x (4 chunks x {Wh, Wl})
#pragma unroll 1
    for (int vv = 0; vv < 24; vv++) {
        if (vv < 23) CP_WAIT1(); else CP_WAIT0();
        __syncthreads();
        const uint32_t wb = base + W_OFF + (uint32_t)(vv & 1) * WBUF;
        const int chunk = (vv >> 1) & 3;
        const int part = vv & 1;          // 0=Wh (x Hh, x Hl), 1=Wl (x Hh)

#pragma unroll
        for (int kk = 0; kk < 4; kk++) {
            uint32_t a[2][4];
            {
                int sel = lane >> 3;
                int o = ob + (lane & 7) + ((sel & 1) << 3);
                int k = kk * 16 + ((sel >> 1) << 3);
#pragma unroll
                for (int i = 0; i < 2; i++)
                    ldsm4(a[i], w_addr(wb, o + i * 16, k));
            }
#pragma unroll
            for (int tgt = 0; tgt < 2; tgt++) {
                if (part && tgt) break;                      // Wl: Hh only
                int kh = (part ? 0 : tgt * 256) + chunk * 64 + kk * 16;
                uint32_t b[4][2];
                {
                    int sel = lane >> 3;
                    int n0 = nb + (lane & 7) + ((sel >> 1) << 3);
                    int k = kh + ((sel & 1) << 3);
#pragma unroll
                    for (int jj = 0; jj < 2; jj++) {
                        uint32_t r[4];
                        ldsm4(r, h_addr(hb, n0 + jj * 16, k));
                        b[2 * jj][0] = r[0]; b[2 * jj][1] = r[1];
                        b[2 * jj + 1][0] = r[2]; b[2 * jj + 1][1] = r[3];
                    }
                }
#pragma unroll
                for (int i = 0; i < 2; i++)
#pragma unroll
                    for (int j = 0; j < 4; j++)
                        mma_bf16(acc[i][j], a[i], b[j]);
            }
        }
        __syncthreads();                 // all warps done reading buf[vv&1]
        if (vv + 2 < 24) {
            stage_w(base + W_OFF + (uint32_t)(vv & 1) * WBUF, vv + 2, tid);
            CP_COMMIT();
        }

        if ((vv & 7) == 7) {             // ---- layer epilogue ----
            const int l = vv >> 3;
            if (l < 2) {
                // 1) acc -> D (fp32 overlay on H region)
#pragma unroll
                for (int i = 0; i < 2; i++) {
                    int o = ob + i * 16 + (lane >> 2);
#pragma unroll
                    for (int j = 0; j < 4; j++) {
                        int n = nb + j * 8 + 2 * (lane & 3);
                        sts_f32(d_addr(hb, n, o),     acc[i][j][0]);
                        sts_f32(d_addr(hb, n + 1, o), acc[i][j][1]);
                        sts_f32(d_addr(hb, n, o + 8),     acc[i][j][2]);
                        sts_f32(d_addr(hb, n + 1, o + 8), acc[i][j][3]);
                    }
                }
                __syncthreads();
                // 2) channel o = tid&255, sample s = tid>>8 (one per group,
                //    all 1024 threads active; du[13] = 26 regs only)
                const int o = tid & 255;
                const int s = tid >> 8;
                ull du[13];
                {
                    float tv[26];
                    tv[25] = 0.f;
#pragma unroll
                    for (int u = 0; u < 25; u++)
                        tv[u] = lds_f32(d_addr(hb, s * 32 + u, o));
#pragma unroll
                    for (int j = 0; j < 13; j++)
                        du[j] = (ull)__float_as_uint(tv[2 * j])
                              | ((ull)__float_as_uint(tv[2 * j + 1]) << 32);
                }
                __syncthreads();
                // 3) A^T mult + bias + lrelu + re-split into H
                float bb = lds_f32(base + BIAS_OFF + (l * 256 + o) * 4);
#pragma unroll 5
                for (int v = 0; v < VDIM; v++) {
                    ull accv = 0ull;
#pragma unroll
                    for (int j = 0; j < 13; j++)
                        accv = fma2(du[j],
                                    lds_u64(base + AS2_OFF + (v * 13 + j) * 8),
                                    accv);
                    float a0, a1;
                    asm("mov.b64 {%0,%1}, %2;" : "=f"(a0), "=f"(a1) : "l"(accv));
                    float r = a0 + a1 + bb;
                    r = (r >= 0.f) ? r : NEG_SLOPE * r;
                    uint16_t hi, lo;
                    split2(r, hi, lo);
                    int nr = s * 32 + v;
                    sts_u16(h_addr(hb, nr, o), hi);
                    sts_u16(h_addr(hb, nr, 256 + o), lo);
                }
                __syncthreads();
            } else {
                // final layer: bias + direct gmem store from fragments
#pragma unroll
                for (int i = 0; i < 2; i++) {
                    int o0 = ob + i * 16 + (lane >> 2);
                    float bb0 = lds_f32(base + BIAS_OFF + (512 + o0) * 4);
                    float bb1 = lds_f32(base + BIAS_OFF + (512 + o0 + 8) * 4);
#pragma unroll
                    for (int j = 0; j < 4; j++) {
                        int n = nb + j * 8 + 2 * (lane & 3);
                        int s = n >> 5, v = n & 31;
                        size_t o_base = ((size_t)(blk * NSAMP + s)) * (CDIM * VDIM);
                        if (v < VDIM) {
                            out[o_base + o0 * VDIM + v] = acc[i][j][0] + bb0;
                            out[o_base + (o0 + 8) * VDIM + v] = acc[i][j][2] + bb1;
                        }
                        if (v + 1 < VDIM) {
                            out[o_base + o0 * VDIM + v + 1] = acc[i][j][1] + bb0;
                            out[o_base + (o0 + 8) * VDIM + v + 1] = acc[i][j][3] + bb1;
                        }
                    }
                }
            }
            // reset accumulators for next layer
#pragma unroll
            for (int i = 0; i < 2; i++)
#pragma unroll
                for (int j = 0; j < 4; j++)
#pragma unroll
                    for (int e = 0; e < 4; e++) acc[i][j][e] = 0.f;
        }
    }
}

// ---------------------------------------------------------------------------
extern "C" void kernel_launch(void* const* d_in, const int* in_sizes, int n_in,
                              void* d_out, int out_size) {
    const float* x  = (const float*)d_in[0];
    const float* A  = (const float*)d_in[1];
    const float* w1 = (const float*)d_in[2];
    const float* b1 = (const float*)d_in[3];
    const float* w2 = (const float*)d_in[4];
    const float* b2 = (const float*)d_in[5];
    const float* wp = (const float*)d_in[6];
    const float* bp = (const float*)d_in[7];
    const int*   t  = (const int*)d_in[8];
    float* out = (float*)d_out;

    const int B = in_sizes[0] / (CDIM * VDIM);   // 4096

    cudaFuncSetAttribute(ode_main, cudaFuncAttributeMaxDynamicSharedMemorySize,
                         SMEM_DYN);

    prep_kernel<<<(PE_N + WS_N + 255) / 256, 256>>>(w1, w2, wp);
    ode_main<<<B / NSAMP, NTHR, SMEM_DYN>>>(x, A, b1, b2, bp, t, out);
}

// round 12
// speedup vs baseline: 1.0942x; 1.0942x over previous
#include <cuda_runtime.h>
#include <cuda_bf16.h>
#include <cstdint>

typedef unsigned long long ull;

#define CDIM 256
#define VDIM 25
#define NSAMP 2
#define PE_LEN 89
#define NEG_SLOPE 0.01f
#define NTHR 256

// ---- SMEM offsets from 1024-aligned base (per CTA ~103KB -> 2 CTAs/SM) ----
#define H_OFF    0u          // 64 rows x 1024 B (Hh k<256 | Hl k>=256), also D
#define W_OFF    65536u      // 2 x 16 KB W chunk buffers
#define WBUF     16384u
#define AS2_OFF  98304u      // 25 x 13 packed f32x2 A rows = 2600 B
#define BIAS_OFF 100928u     // 3 x 256 f32 = 3072 B
#define SMEM_DYN 105472u     // 104000 + align slack; 2x105472 = 210944 <= 227KB

// ---------------------------------------------------------------------------
// helpers
// ---------------------------------------------------------------------------
__device__ __forceinline__ uint32_t smem_u32(const void* p) {
    uint32_t a;
    asm("{ .reg .u64 t; cvta.to.shared.u64 t, %1; cvt.u32.u64 %0, t; }"
        : "=r"(a) : "l"(p));
    return a;
}
__device__ __forceinline__ ull fma2(ull a, ull b, ull c) {
    ull d;
    asm("fma.rn.f32x2 %0, %1, %2, %3;" : "=l"(d) : "l"(a), "l"(b), "l"(c));
    return d;
}
__device__ __forceinline__ void cpasync16(uint32_t dst, const void* src) {
    asm volatile("cp.async.cg.shared.global [%0], [%1], 16;" :: "r"(dst), "l"(src));
}
#define CP_COMMIT() asm volatile("cp.async.commit_group;" ::: "memory")
#define CP_WAIT1()  asm volatile("cp.async.wait_group 1;" ::: "memory")
#define CP_WAIT0()  asm volatile("cp.async.wait_group 0;" ::: "memory")

__device__ __forceinline__ void ldsm4(uint32_t* r, uint32_t a) {
    asm volatile("ldmatrix.sync.aligned.m8n8.x4.shared.b16 {%0,%1,%2,%3}, [%4];"
        : "=r"(r[0]), "=r"(r[1]), "=r"(r[2]), "=r"(r[3]) : "r"(a));
}
__device__ __forceinline__ void mma_bf16(float* d, const uint32_t* a,
                                         const uint32_t* b) {
    asm volatile(
        "mma.sync.aligned.m16n8k16.row.col.f32.bf16.bf16.f32 "
        "{%0,%1,%2,%3}, {%4,%5,%6,%7}, {%8,%9}, {%0,%1,%2,%3};"
        : "+f"(d[0]), "+f"(d[1]), "+f"(d[2]), "+f"(d[3])
        : "r"(a[0]), "r"(a[1]), "r"(a[2]), "r"(a[3]), "r"(b[0]), "r"(b[1]));
}
__device__ __forceinline__ void sts_f32(uint32_t a, float v) {
    asm volatile("st.shared.f32 [%0], %1;" :: "r"(a), "f"(v));
}
__device__ __forceinline__ float lds_f32(uint32_t a) {
    float v; asm volatile("ld.shared.f32 %0, [%1];" : "=f"(v) : "r"(a)); return v;
}
__device__ __forceinline__ void sts_u16(uint32_t a, uint16_t v) {
    asm volatile("st.shared.u16 [%0], %1;" :: "r"(a), "h"(v));
}
__device__ __forceinline__ ull lds_u64(uint32_t a) {
    ull v; asm volatile("ld.shared.b64 %0, [%1];" : "=l"(v) : "r"(a)); return v;
}
__device__ __forceinline__ void sts_u64(uint32_t a, ull v) {
    asm volatile("st.shared.b64 [%0], %1;" :: "r"(a), "l"(v));
}
__device__ __forceinline__ void sts_z16(uint32_t a) {
    asm volatile("st.shared.v4.b32 [%0], {%1,%1,%1,%1};" :: "r"(a), "r"(0u));
}

// H tile: [n row (0..63)] x [k (0..511)] bf16, 1024 B rows, XOR-swizzled
__device__ __forceinline__ uint32_t h_addr(uint32_t hb, int n, int k) {
    return hb + n * 1024 + ((((k >> 3) ^ (n & 7)) << 4) | ((k & 7) << 1));
}
// W chunk buffer: 256 o x 32 k bf16; o-pairs share a 128B row:
//   byte = (o>>1)*128 + (o&1)*64 + swizzled 16B unit; unit ^= (o>>1)&3
//   -> 8-row ldsm phases hit 8 distinct 16B slots (conflict-free)
__device__ __forceinline__ uint32_t w_addr(uint32_t wb, int o, int k) {
    return wb + (uint32_t)(o >> 1) * 128 + ((o & 1) << 6)
         + ((((k >> 3) ^ ((o >> 1) & 3)) << 4) | ((k & 7) << 1));
}
// D (fp32) overlay in H region: [n][o], XOR-swizzled
__device__ __forceinline__ uint32_t d_addr(uint32_t hb, int n, int o) {
    return hb + n * 1024 + ((o ^ ((n & 7) << 2)) << 2);
}

__device__ __forceinline__ void split2(float v, uint16_t& hi, uint16_t& lo) {
    __nv_bfloat16 h = __float2bfloat16(v);
    __nv_bfloat16 l = __float2bfloat16(v - __bfloat162float(h));
    hi = __bfloat16_as_ushort(h);
    lo = __bfloat16_as_ushort(l);
}

// ---------------------------------------------------------------------------
// device globals + single merged prep kernel
// ---------------------------------------------------------------------------
__device__ float g_pe[PE_LEN * CDIM];
__device__ __nv_bfloat16 g_ws[3 * 2 * 256 * 256];   // [layer][part(hi/lo)][o][c]

#define PE_N   (PE_LEN * CDIM)
#define WS_N   (3 * CDIM * CDIM)

__global__ void prep_kernel(const float* __restrict__ w1,
                            const float* __restrict__ w2,
                            const float* __restrict__ wp) {
    int idx = blockIdx.x * blockDim.x + threadIdx.x;
    if (idx < PE_N) {
        int row = idx / CDIM, c = idx % CDIM;
        int p2 = (c >> 1) * 2;
        float divf = expf((float)p2 * (-9.210340371976184f / 256.0f));
        double ang = (double)row * (double)divf;
        g_pe[idx] = (c & 1) ? (float)cos(ang) : (float)sin(ang);
    } else if (idx < PE_N + WS_N) {
        int i = idx - PE_N;
        int l = i / (CDIM * CDIM), rem = i % (CDIM * CDIM);
        const float* w = (l == 0) ? w1 : ((l == 1) ? w2 : wp);
        float v = w[rem];
        __nv_bfloat16 h = __float2bfloat16(v);
        __nv_bfloat16 lo = __float2bfloat16(v - __bfloat162float(h));
        g_ws[((size_t)(l * 2 + 0) * 256) * 256 + rem] = h;
        g_ws[((size_t)(l * 2 + 1) * 256) * 256 + rem] = lo;
    }
}

// stage W virtual chunk vv (layer=vv>>4, part=vv&1, chunk=(vv>>1)&7) -> buf
// chunk = 256 o-rows x 32 k-cols bf16 = 16 KB; 1024 cp.async16 / 256 thr
__device__ __forceinline__ void stage_w(uint32_t wb, int vv, int tid) {
    const __nv_bfloat16* src = g_ws
        + ((size_t)((vv >> 4) * 2 + (vv & 1)) * 256) * 256
        + (size_t)(((vv >> 1) & 7) * 32);
#pragma unroll
    for (int q = 0; q < 4; q++) {
        int t = tid + q * NTHR;
        int o = t >> 2, k8 = (t & 3) << 3;
        cpasync16(w_addr(wb, o, k8), src + (size_t)o * 256 + k8);
    }
}

// ---------------------------------------------------------------------------
// main kernel: 1 CTA = 2 samples, 256 threads (8 warps, 4x2 warp grid,
// warp tile 64x32); ~103KB smem -> 2 CTAs/SM for cross-CTA latency hiding
// ---------------------------------------------------------------------------
__global__ void __launch_bounds__(NTHR, 2)
ode_main(const float* __restrict__ x, const float* __restrict__ A,
         const float* __restrict__ b1, const float* __restrict__ b2,
         const float* __restrict__ bp, const int* __restrict__ tptr,
         float* __restrict__ out) {
    extern __shared__ char raw[];
    uint32_t rawu = smem_u32(raw);
    uint32_t base = (rawu + 1023u) & ~1023u;

    const int tid = threadIdx.x, lane = tid & 31, wid = tid >> 5;
    const int blk = blockIdx.x;
    const uint32_t hb = base + H_OFF;
    const int ob = (wid >> 1) * 64;     // warp m-tile origin (o), 4 tiles
    const int nb = (wid & 1) * 32;      // warp n-tile origin (rows), 2 tiles

    // kick off W prefetch for vchunks 0, 1 immediately
    stage_w(base + W_OFF, 0, tid);          CP_COMMIT();
    stage_w(base + W_OFF + WBUF, 1, tid);   CP_COMMIT();

    // stage A (packed f32x2 rows) + biases
    for (int i = tid; i < VDIM * 13; i += NTHR) {
        int v = i / 13, j = i % 13, u0 = 2 * j, u1 = 2 * j + 1;
        float f0 = A[v * VDIM + u0];
        float f1 = (u1 < VDIM) ? A[v * VDIM + u1] : 0.f;
        ull p = (ull)__float_as_uint(f0) | ((ull)__float_as_uint(f1) << 32);
        sts_u64(base + AS2_OFF + i * 8, p);
    }
    for (int i = tid; i < 768; i += NTHR) {
        float bv = (i < 256) ? b1[i] : ((i < 512) ? b2[i - 256] : bp[i - 512]);
        sts_f32(base + BIAS_OFF + i * 4, bv);
    }

    // build H = split(x + pe): Hh at k=c, Hl at k=256+c; rows n = s*32+v
    const int t0 = *tptr;
    for (int i = tid; i < NSAMP * CDIM * VDIM; i += NTHR) {
        int s = i / (CDIM * VDIM);
        int rem = i - s * (CDIM * VDIM);
        int c = rem / VDIM, v = rem - c * VDIM;
        int n = blk * NSAMP + s;
        float val = x[(size_t)n * (CDIM * VDIM) + rem]
                  + g_pe[(t0 + (n & 63)) * CDIM + c];
        uint16_t hi, lo;
        split2(val, hi, lo);
        int nr = s * 32 + v;
        sts_u16(h_addr(hb, nr, c), hi);
        sts_u16(h_addr(hb, nr, 256 + c), lo);
    }
    // zero pad rows v=25..31 (2 samples x 7 rows x 1024 B = 14*64 units)
    for (int i = tid; i < 14 * 64; i += NTHR) {
        int r = i >> 6;
        int s = r / 7, v = 25 + (r % 7);
        sts_z16(hb + (s * 32 + v) * 1024 + (i & 63) * 16);
    }
    __syncthreads();

    float acc[4][4][4];
#pragma unroll
    for (int i = 0; i < 4; i++)
#pragma unroll
        for (int j = 0; j < 4; j++)
#pragma unroll
            for (int e = 0; e < 4; e++) acc[i][j][e] = 0.f;

    // 48 virtual chunks: 3 layers x (8 chunks x {Wh, Wl})
#pragma unroll 1
    for (int vv = 0; vv < 48; vv++) {
        if (vv < 47) CP_WAIT1(); else CP_WAIT0();
        __syncthreads();
        const uint32_t wb = base + W_OFF + (uint32_t)(vv & 1) * WBUF;
        const int chunk = (vv >> 1) & 7;
        const int part = vv & 1;          // 0=Wh (x Hh, x Hl), 1=Wl (x Hh)

#pragma unroll
        for (int kk = 0; kk < 2; kk++) {
            uint32_t a[4][4];
            {
                int sel = lane >> 3;
                int o = ob + (lane & 7) + ((sel & 1) << 3);
                int k = kk * 16 + ((sel >> 1) << 3);
#pragma unroll
                for (int i = 0; i < 4; i++)
                    ldsm4(a[i], w_addr(wb, o + i * 16, k));
            }
#pragma unroll
            for (int tgt = 0; tgt < 2; tgt++) {
                if (part && tgt) break;                      // Wl: Hh only
                int kh = (part ? 0 : tgt * 256) + chunk * 32 + kk * 16;
                uint32_t b[4][2];
                {
                    int sel = lane >> 3;
                    int n0 = nb + (lane & 7) + ((sel >> 1) << 3);
                    int k = kh + ((sel & 1) << 3);
#pragma unroll
                    for (int jj = 0; jj < 2; jj++) {
                        uint32_t r[4];
                        ldsm4(r, h_addr(hb, n0 + jj * 16, k));
                        b[2 * jj][0] = r[0]; b[2 * jj][1] = r[1];
                        b[2 * jj + 1][0] = r[2]; b[2 * jj + 1][1] = r[3];
                    }
                }
#pragma unroll
                for (int i = 0; i < 4; i++)
#pragma unroll
                    for (int j = 0; j < 4; j++)
                        mma_bf16(acc[i][j], a[i], b[j]);
            }
        }
        __syncthreads();                 // all warps done reading buf[vv&1]
        if (vv + 2 < 48) {
            stage_w(base + W_OFF + (uint32_t)(vv & 1) * WBUF, vv + 2, tid);
            CP_COMMIT();
        }

        if ((vv & 15) == 15) {           // ---- layer epilogue ----
            const int l = vv >> 4;
            if (l < 2) {
                // 1) acc -> D (fp32 overlay on H region)
#pragma unroll
                for (int i = 0; i < 4; i++) {
                    int o = ob + i * 16 + (lane >> 2);
#pragma unroll
                    for (int j = 0; j < 4; j++) {
                        int n = nb + j * 8 + 2 * (lane & 3);
                        sts_f32(d_addr(hb, n, o),     acc[i][j][0]);
                        sts_f32(d_addr(hb, n + 1, o), acc[i][j][1]);
                        sts_f32(d_addr(hb, n, o + 8),     acc[i][j][2]);
                        sts_f32(d_addr(hb, n + 1, o + 8), acc[i][j][3]);
                    }
                }
                __syncthreads();
                // 2) channel o = tid; both samples' D rows into regs
                const int o = tid;
                ull du[NSAMP][13];
#pragma unroll
                for (int s = 0; s < NSAMP; s++) {
                    float tv[26];
                    tv[25] = 0.f;
#pragma unroll
                    for (int u = 0; u < 25; u++)
                        tv[u] = lds_f32(d_addr(hb, s * 32 + u, o));
#pragma unroll
                    for (int j = 0; j < 13; j++)
                        du[s][j] = (ull)__float_as_uint(tv[2 * j])
                                 | ((ull)__float_as_uint(tv[2 * j + 1]) << 32);
                }
                __syncthreads();
                // 3) A^T mult + bias + lrelu + re-split into H (v-outer)
                float bb = lds_f32(base + BIAS_OFF + (l * 256 + o) * 4);
#pragma unroll 5
                for (int v = 0; v < VDIM; v++) {
                    ull ar[13];
#pragma unroll
                    for (int j = 0; j < 13; j++)
                        ar[j] = lds_u64(base + AS2_OFF + (v * 13 + j) * 8);
#pragma unroll
                    for (int s = 0; s < NSAMP; s++) {
                        ull accv = 0ull;
#pragma unroll
                        for (int j = 0; j < 13; j++)
                            accv = fma2(du[s][j], ar[j], accv);
                        float a0, a1;
                        asm("mov.b64 {%0,%1}, %2;" : "=f"(a0), "=f"(a1) : "l"(accv));
                        float r = a0 + a1 + bb;
                        r = (r >= 0.f) ? r : NEG_SLOPE * r;
                        uint16_t hi, lo;
                        split2(r, hi, lo);
                        int nr = s * 32 + v;
                        sts_u16(h_addr(hb, nr, o), hi);
                        sts_u16(h_addr(hb, nr, 256 + o), lo);
                    }
                }
                __syncthreads();
            } else {
                // final layer: bias + direct gmem store from fragments
#pragma unroll
                for (int i = 0; i < 4; i++) {
                    int o0 = ob + i * 16 + (lane >> 2);
                    float bb0 = lds_f32(base + BIAS_OFF + (512 + o0) * 4);
                    float bb1 = lds_f32(base + BIAS_OFF + (512 + o0 + 8) * 4);
#pragma unroll
                    for (int j = 0; j < 4; j++) {
                        int n = nb + j * 8 + 2 * (lane & 3);
                        int s = n >> 5, v = n & 31;
                        size_t o_base = ((size_t)(blk * NSAMP + s)) * (CDIM * VDIM);
                        if (v < VDIM) {
                            out[o_base + o0 * VDIM + v] = acc[i][j][0] + bb0;
                            out[o_base + (o0 + 8) * VDIM + v] = acc[i][j][2] + bb1;
                        }
                        if (v + 1 < VDIM) {
                            out[o_base + o0 * VDIM + v + 1] = acc[i][j][1] + bb0;
                            out[o_base + (o0 + 8) * VDIM + v + 1] = acc[i][j][3] + bb1;
                        }
                    }
                }
            }
            // reset accumulators for next layer
#pragma unroll
            for (int i = 0; i < 4; i++)
#pragma unroll
                for (int j = 0; j < 4; j++)
#pragma unroll
                    for (int e = 0; e < 4; e++) acc[i][j][e] = 0.f;
        }
    }
}

// ---------------------------------------------------------------------------
extern "C" void kernel_launch(void* const* d_in, const int* in_sizes, int n_in,
                              void* d_out, int out_size) {
    const float* x  = (const float*)d_in[0];
    const float* A  = (const float*)d_in[1];
    const float* w1 = (const float*)d_in[2];
    const float* b1 = (const float*)d_in[3];
    const float* w2 = (const float*)d_in[4];
    const float* b2 = (const float*)d_in[5];
    const float* wp = (const float*)d_in[6];
    const float* bp = (const float*)d_in[7];
    const int*   t  = (const int*)d_in[8];
    float* out = (float*)d_out;

    const int B = in_sizes[0] / (CDIM * VDIM);   // 4096

    cudaFuncSetAttribute(ode_main, cudaFuncAttributeMaxDynamicSharedMemorySize,
                         SMEM_DYN);

    prep_kernel<<<(PE_N + WS_N + 255) / 256, 256>>>(w1, w2, wp);
    ode_main<<<B / NSAMP, NTHR, SMEM_DYN>>>(x, A, b1, b2, bp, t, out);
}

// round 14
// speedup vs baseline: 1.1339x; 1.0363x over previous
#include <cuda_runtime.h>
#include <cuda_bf16.h>
#include <cstdint>

typedef unsigned long long ull;

#define CDIM 256
#define VDIM 25
#define NSAMP 2
#define PE_LEN 89
#define NEG_SLOPE 0.01f
#define NTHR 256

// ---- SMEM offsets from 1024-aligned base ----
// H: 50 rows x 1024 B (real data; ldsm may read rows 50..63 = garbage into W
// region -> outputs from those rows are never stored)
#define H_OFF    0u
#define W_OFF    51200u      // 3 x 16 KB W chunk buffers (depth-3 pipeline)
#define WBUF     16384u
#define AS2_OFF  100352u     // 25 x 13 packed f32x2 A rows = 2600 B
#define BIAS_OFF 102976u     // 3 x 256 f32
#define SMEM_DYN 107520u     // x2 CTAs = 215040 <= 227KB/SM

// ---------------------------------------------------------------------------
// helpers
// ---------------------------------------------------------------------------
__device__ __forceinline__ uint32_t smem_u32(const void* p) {
    uint32_t a;
    asm("{ .reg .u64 t; cvta.to.shared.u64 t, %1; cvt.u32.u64 %0, t; }"
        : "=r"(a) : "l"(p));
    return a;
}
__device__ __forceinline__ ull fma2(ull a, ull b, ull c) {
    ull d;
    asm("fma.rn.f32x2 %0, %1, %2, %3;" : "=l"(d) : "l"(a), "l"(b), "l"(c));
    return d;
}
__device__ __forceinline__ void cpasync16(uint32_t dst, const void* src) {
    asm volatile("cp.async.cg.shared.global [%0], [%1], 16;" :: "r"(dst), "l"(src));
}
#define CP_COMMIT() asm volatile("cp.async.commit_group;" ::: "memory")
#define CP_WAITN(n) asm volatile("cp.async.wait_group %0;" :: "n"(n) : "memory")

__device__ __forceinline__ void ldsm4(uint32_t* r, uint32_t a) {
    asm volatile("ldmatrix.sync.aligned.m8n8.x4.shared.b16 {%0,%1,%2,%3}, [%4];"
        : "=r"(r[0]), "=r"(r[1]), "=r"(r[2]), "=r"(r[3]) : "r"(a));
}
__device__ __forceinline__ void mma_bf16(float* d, const uint32_t* a,
                                         const uint32_t* b) {
    asm volatile(
        "mma.sync.aligned.m16n8k16.row.col.f32.bf16.bf16.f32 "
        "{%0,%1,%2,%3}, {%4,%5,%6,%7}, {%8,%9}, {%0,%1,%2,%3};"
        : "+f"(d[0]), "+f"(d[1]), "+f"(d[2]), "+f"(d[3])
        : "r"(a[0]), "r"(a[1]), "r"(a[2]), "r"(a[3]), "r"(b[0]), "r"(b[1]));
}
__device__ __forceinline__ void sts_f32(uint32_t a, float v) {
    asm volatile("st.shared.f32 [%0], %1;" :: "r"(a), "f"(v));
}
__device__ __forceinline__ float lds_f32(uint32_t a) {
    float v; asm volatile("ld.shared.f32 %0, [%1];" : "=f"(v) : "r"(a)); return v;
}
__device__ __forceinline__ void sts_u16(uint32_t a, uint16_t v) {
    asm volatile("st.shared.u16 [%0], %1;" :: "r"(a), "h"(v));
}
__device__ __forceinline__ ull lds_u64(uint32_t a) {
    ull v; asm volatile("ld.shared.b64 %0, [%1];" : "=l"(v) : "r"(a)); return v;
}
__device__ __forceinline__ void sts_u64(uint32_t a, ull v) {
    asm volatile("st.shared.b64 [%0], %1;" :: "r"(a), "l"(v));
}

// H tile: [n row] x [k (0..511)] bf16, 1024 B rows, XOR-swizzled
__device__ __forceinline__ uint32_t h_addr(uint32_t hb, int n, int k) {
    return hb + n * 1024 + ((((k >> 3) ^ (n & 7)) << 4) | ((k & 7) << 1));
}
// W chunk buffer: 256 o x 32 k bf16; o-pairs share a 128B row (swizzled)
__device__ __forceinline__ uint32_t w_addr(uint32_t wb, int o, int k) {
    return wb + (uint32_t)(o >> 1) * 128 + ((o & 1) << 6)
         + ((((k >> 3) ^ ((o >> 1) & 3)) << 4) | ((k & 7) << 1));
}
// D (fp32) overlay in H region: [n][o], XOR-swizzled
__device__ __forceinline__ uint32_t d_addr(uint32_t hb, int n, int o) {
    return hb + n * 1024 + ((o ^ ((n & 7) << 2)) << 2);
}

__device__ __forceinline__ void split2(float v, uint16_t& hi, uint16_t& lo) {
    __nv_bfloat16 h = __float2bfloat16(v);
    __nv_bfloat16 l = __float2bfloat16(v - __bfloat162float(h));
    hi = __bfloat16_as_ushort(h);
    lo = __bfloat16_as_ushort(l);
}

// ---------------------------------------------------------------------------
// device globals + single merged prep kernel
// ---------------------------------------------------------------------------
__device__ float g_pe[PE_LEN * CDIM];
__device__ __nv_bfloat16 g_ws[3 * 2 * 256 * 256];   // [layer][part(hi/lo)][o][c]

#define PE_N   (PE_LEN * CDIM)
#define WS_N   (3 * CDIM * CDIM)

__global__ void prep_kernel(const float* __restrict__ w1,
                            const float* __restrict__ w2,
                            const float* __restrict__ wp) {
    int idx = blockIdx.x * blockDim.x + threadIdx.x;
    if (idx < PE_N) {
        int row = idx / CDIM, c = idx % CDIM;
        int p2 = (c >> 1) * 2;
        float divf = expf((float)p2 * (-9.210340371976184f / 256.0f));
        double ang = (double)row * (double)divf;
        g_pe[idx] = (c & 1) ? (float)cos(ang) : (float)sin(ang);
    } else if (idx < PE_N + WS_N) {
        int i = idx - PE_N;
        int l = i / (CDIM * CDIM), rem = i % (CDIM * CDIM);
        const float* w = (l == 0) ? w1 : ((l == 1) ? w2 : wp);
        float v = w[rem];
        __nv_bfloat16 h = __float2bfloat16(v);
        __nv_bfloat16 lo = __float2bfloat16(v - __bfloat162float(h));
        g_ws[((size_t)(l * 2 + 0) * 256) * 256 + rem] = h;
        g_ws[((size_t)(l * 2 + 1) * 256) * 256 + rem] = lo;
    }
}

// stage W chunk vv (layer=vv>>4, part=vv&1, chunk=(vv>>1)&7) -> buffer
__device__ __forceinline__ void stage_w(uint32_t wb, int vv, int tid) {
    const __nv_bfloat16* src = g_ws
        + ((size_t)((vv >> 4) * 2 + (vv & 1)) * 256) * 256
        + (size_t)(((vv >> 1) & 7) * 32);
#pragma unroll
    for (int q = 0; q < 4; q++) {
        int t = tid + q * NTHR;
        int o = t >> 2, k8 = (t & 3) << 3;
        cpasync16(w_addr(wb, o, k8), src + (size_t)o * 256 + k8);
    }
}

// ---------------------------------------------------------------------------
// main kernel: 1 CTA = 2 samples (rows n = s*25+v, 50 real of 56 computed);
// 256 threads = 8 warps, uniform warp tile 32(o) x 56(rows); 2 CTAs/SM
// ---------------------------------------------------------------------------
__global__ void __launch_bounds__(NTHR, 2)
ode_main(const float* __restrict__ x, const float* __restrict__ A,
         const float* __restrict__ b1, const float* __restrict__ b2,
         const float* __restrict__ bp, const int* __restrict__ tptr,
         float* __restrict__ out) {
    extern __shared__ char raw[];
    uint32_t rawu = smem_u32(raw);
    uint32_t base = (rawu + 1023u) & ~1023u;

    const int tid = threadIdx.x, lane = tid & 31, wid = tid >> 5;
    const int blk = blockIdx.x;
    const uint32_t hb = base + H_OFF;
    const int ob = wid * 32;            // warp m-tile origin (o), 8 warps

    // depth-3 pipeline prologue: stage chunks 0,1,2
    stage_w(base + W_OFF,            0, tid); CP_COMMIT();
    stage_w(base + W_OFF + WBUF,     1, tid); CP_COMMIT();
    stage_w(base + W_OFF + 2 * WBUF, 2, tid); CP_COMMIT();

    // stage A (packed f32x2 rows) + biases
    for (int i = tid; i < VDIM * 13; i += NTHR) {
        int v = i / 13, j = i % 13, u0 = 2 * j, u1 = 2 * j + 1;
        float f0 = A[v * VDIM + u0];
        float f1 = (u1 < VDIM) ? A[v * VDIM + u1] : 0.f;
        ull p = (ull)__float_as_uint(f0) | ((ull)__float_as_uint(f1) << 32);
        sts_u64(base + AS2_OFF + i * 8, p);
    }
    for (int i = tid; i < 768; i += NTHR) {
        float bv = (i < 256) ? b1[i] : ((i < 512) ? b2[i - 256] : bp[i - 512]);
        sts_f32(base + BIAS_OFF + i * 4, bv);
    }

    // build H = split(x + pe): rows n = s*25+v (no zero-padding needed:
    // pad-row outputs are never stored)
    const int t0 = *tptr;
    for (int i = tid; i < NSAMP * CDIM * VDIM; i += NTHR) {
        int s = i / (CDIM * VDIM);
        int rem = i - s * (CDIM * VDIM);
        int c = rem / VDIM, v = rem - c * VDIM;
        int n = blk * NSAMP + s;
        float val = x[(size_t)n * (CDIM * VDIM) + rem]
                  + g_pe[(t0 + (n & 63)) * CDIM + c];
        uint16_t hi, lo;
        split2(val, hi, lo);
        int nr = s * VDIM + v;
        sts_u16(h_addr(hb, nr, c), hi);
        sts_u16(h_addr(hb, nr, 256 + c), lo);
    }
    __syncthreads();

    float acc[2][7][4];
#pragma unroll
    for (int i = 0; i < 2; i++)
#pragma unroll
        for (int j = 0; j < 7; j++)
#pragma unroll
            for (int e = 0; e < 4; e++) acc[i][j][e] = 0.f;

    // 48 chunks: 3 layers x (8 chunks x {Wh, Wl})
#pragma unroll 1
    for (int vv = 0; vv < 48; vv++) {
        if (vv < 46) CP_WAITN(2);
        else if (vv == 46) CP_WAITN(1);
        else CP_WAITN(0);
        __syncthreads();
        const uint32_t wb = base + W_OFF + (uint32_t)(vv % 3) * WBUF;
        const int chunk = (vv >> 1) & 7;
        const int part = vv & 1;          // 0=Wh (x Hh, x Hl), 1=Wl (x Hh)

#pragma unroll
        for (int kk = 0; kk < 2; kk++) {
            uint32_t a[2][4];
            {
                int sel = lane >> 3;
                int o = ob + (lane & 7) + ((sel & 1) << 3);
                int k = kk * 16 + ((sel >> 1) << 3);
#pragma unroll
                for (int i = 0; i < 2; i++)
                    ldsm4(a[i], w_addr(wb, o + i * 16, k));
            }
#pragma unroll
            for (int tgt = 0; tgt < 2; tgt++) {
                if (part && tgt) break;                      // Wl: Hh only
                int kh = (part ? 0 : tgt * 256) + chunk * 32 + kk * 16;
                uint32_t b[8][2];
                {
                    int sel = lane >> 3;
                    int n0 = (lane & 7) + ((sel >> 1) << 3);
                    int k = kh + ((sel & 1) << 3);
#pragma unroll
                    for (int jj = 0; jj < 4; jj++) {
                        uint32_t r[4];
                        ldsm4(r, h_addr(hb, n0 + jj * 16, k));
                        b[2 * jj][0] = r[0]; b[2 * jj][1] = r[1];
                        b[2 * jj + 1][0] = r[2]; b[2 * jj + 1][1] = r[3];
                    }
                }
#pragma unroll
                for (int i = 0; i < 2; i++)
#pragma unroll
                    for (int j = 0; j < 7; j++)
                        mma_bf16(acc[i][j], a[i], b[j]);
            }
        }
        __syncthreads();                 // all warps done reading buf vv%3
        if (vv + 3 < 48) {
            stage_w(base + W_OFF + (uint32_t)(vv % 3) * WBUF, vv + 3, tid);
            CP_COMMIT();
        }

        if ((vv & 15) == 15) {           // ---- layer epilogue ----
            const int l = vv >> 4;
            if (l < 2) {
                // 1) acc -> D (fp32 overlay on H region), skip pad rows
#pragma unroll
                for (int i = 0; i < 2; i++) {
                    int o = ob + i * 16 + (lane >> 2);
#pragma unroll
                    for (int j = 0; j < 7; j++) {
                        int n = j * 8 + 2 * (lane & 3);
                        if (n < 50) {
                            sts_f32(d_addr(hb, n, o),     acc[i][j][0]);
                            sts_f32(d_addr(hb, n, o + 8), acc[i][j][2]);
                        }
                        if (n + 1 < 50) {
                            sts_f32(d_addr(hb, n + 1, o),     acc[i][j][1]);
                            sts_f32(d_addr(hb, n + 1, o + 8), acc[i][j][3]);
                        }
                    }
                }
                __syncthreads();
                // 2) channel o = tid; both samples' D rows into regs
                const int o = tid;
                ull du[NSAMP][13];
#pragma unroll
                for (int s = 0; s < NSAMP; s++) {
                    float tv[26];
                    tv[25] = 0.f;
#pragma unroll
                    for (int u = 0; u < 25; u++)
                        tv[u] = lds_f32(d_addr(hb, s * VDIM + u, o));
#pragma unroll
                    for (int j = 0; j < 13; j++)
                        du[s][j] = (ull)__float_as_uint(tv[2 * j])
                                 | ((ull)__float_as_uint(tv[2 * j + 1]) << 32);
                }
                __syncthreads();
                // 3) A^T mult + bias + lrelu + re-split into H (v-outer)
                float bb = lds_f32(base + BIAS_OFF + (l * 256 + o) * 4);
#pragma unroll 5
                for (int v = 0; v < VDIM; v++) {
                    ull ar[13];
#pragma unroll
                    for (int j = 0; j < 13; j++)
                        ar[j] = lds_u64(base + AS2_OFF + (v * 13 + j) * 8);
#pragma unroll
                    for (int s = 0; s < NSAMP; s++) {
                        ull accv = 0ull;
#pragma unroll
                        for (int j = 0; j < 13; j++)
                            accv = fma2(du[s][j], ar[j], accv);
                        float a0, a1;
                        asm("mov.b64 {%0,%1}, %2;" : "=f"(a0), "=f"(a1) : "l"(accv));
                        float r = a0 + a1 + bb;
                        r = (r >= 0.f) ? r : NEG_SLOPE * r;
                        uint16_t hi, lo;
                        split2(r, hi, lo);
                        int nr = s * VDIM + v;
                        sts_u16(h_addr(hb, nr, o), hi);
                        sts_u16(h_addr(hb, nr, 256 + o), lo);
                    }
                }
                __syncthreads();
            } else {
                // final layer: bias + direct gmem store from fragments
#pragma unroll
                for (int i = 0; i < 2; i++) {
                    int o0 = ob + i * 16 + (lane >> 2);
                    float bb0 = lds_f32(base + BIAS_OFF + (512 + o0) * 4);
                    float bb1 = lds_f32(base + BIAS_OFF + (512 + o0 + 8) * 4);
#pragma unroll
                    for (int j = 0; j < 7; j++) {
                        int n = j * 8 + 2 * (lane & 3);
#pragma unroll
                        for (int e = 0; e < 2; e++) {
                            int r = n + e;
                            if (r < NSAMP * VDIM) {
                                int s = (r >= VDIM) ? 1 : 0;
                                int v = r - s * VDIM;
                                size_t o_base =
                                    ((size_t)(blk * NSAMP + s)) * (CDIM * VDIM);
                                out[o_base + o0 * VDIM + v]
                                    = acc[i][j][e] + bb0;
                                out[o_base + (o0 + 8) * VDIM + v]
                                    = acc[i][j][e + 2] + bb1;
                            }
                        }
                    }
                }
            }
            // reset accumulators for next layer
#pragma unroll
            for (int i = 0; i < 2; i++)
#pragma unroll
                for (int j = 0; j < 7; j++)
#pragma unroll
                    for (int e = 0; e < 4; e++) acc[i][j][e] = 0.f;
        }
    }
}

// ---------------------------------------------------------------------------
extern "C" void kernel_launch(void* const* d_in, const int* in_sizes, int n_in,
                              void* d_out, int out_size) {
    const float* x  = (const float*)d_in[0];
    const float* A  = (const float*)d_in[1];
    const float* w1 = (const float*)d_in[2];
    const float* b1 = (const float*)d_in[3];
    const float* w2 = (const float*)d_in[4];
    const float* b2 = (const float*)d_in[5];
    const float* wp = (const float*)d_in[6];
    const float* bp = (const float*)d_in[7];
    const int*   t  = (const int*)d_in[8];
    float* out = (float*)d_out;

    const int B = in_sizes[0] / (CDIM * VDIM);   // 4096

    cudaFuncSetAttribute(ode_main, cudaFuncAttributeMaxDynamicSharedMemorySize,
                         SMEM_DYN);

    prep_kernel<<<(PE_N + WS_N + 255) / 256, 256>>>(w1, w2, wp);
    ode_main<<<B / NSAMP, NTHR, SMEM_DYN>>>(x, A, b1, b2, bp, t, out);
}

// round 16
// speedup vs baseline: 1.3804x; 1.2174x over previous
#include <cuda_runtime.h>
#include <cuda_bf16.h>
#include <cstdint>

typedef unsigned long long ull;

#define CDIM 256
#define VDIM 25
#define NSAMP 2
#define PE_LEN 89
#define NEG_SLOPE 0.01f
#define NTHR 256

// ---- SMEM offsets from 1024-aligned base ----
// H: rows n = s*25+v (50 real); region reserved to 64 rows so ldsm of pad
// rows 50..63 stays in-bounds (garbage values -> outputs never stored)
#define H_OFF    0u
#define AS2_OFF  65536u      // 25 x 13 packed f32x2 A rows = 2600 B
#define BIAS_OFF 68608u      // 3 x 256 f32 = 3072 B
#define SMEM_DYN 72704u      // x2 CTAs = 145408 <= 227KB/SM

// ---------------------------------------------------------------------------
// helpers
// ---------------------------------------------------------------------------
__device__ __forceinline__ uint32_t smem_u32(const void* p) {
    uint32_t a;
    asm("{ .reg .u64 t; cvta.to.shared.u64 t, %1; cvt.u32.u64 %0, t; }"
        : "=r"(a) : "l"(p));
    return a;
}
__device__ __forceinline__ ull fma2(ull a, ull b, ull c) {
    ull d;
    asm("fma.rn.f32x2 %0, %1, %2, %3;" : "=l"(d) : "l"(a), "l"(b), "l"(c));
    return d;
}
__device__ __forceinline__ void ldsm4(uint32_t* r, uint32_t a) {
    asm volatile("ldmatrix.sync.aligned.m8n8.x4.shared.b16 {%0,%1,%2,%3}, [%4];"
        : "=r"(r[0]), "=r"(r[1]), "=r"(r[2]), "=r"(r[3]) : "r"(a));
}
__device__ __forceinline__ void mma_bf16(float* d, const uint32_t* a,
                                         const uint32_t* b) {
    asm volatile(
        "mma.sync.aligned.m16n8k16.row.col.f32.bf16.bf16.f32 "
        "{%0,%1,%2,%3}, {%4,%5,%6,%7}, {%8,%9}, {%0,%1,%2,%3};"
        : "+f"(d[0]), "+f"(d[1]), "+f"(d[2]), "+f"(d[3])
        : "r"(a[0]), "r"(a[1]), "r"(a[2]), "r"(a[3]), "r"(b[0]), "r"(b[1]));
}
__device__ __forceinline__ void sts_f32(uint32_t a, float v) {
    asm volatile("st.shared.f32 [%0], %1;" :: "r"(a), "f"(v));
}
__device__ __forceinline__ float lds_f32(uint32_t a) {
    float v; asm volatile("ld.shared.f32 %0, [%1];" : "=f"(v) : "r"(a)); return v;
}
__device__ __forceinline__ void sts_u16(uint32_t a, uint16_t v) {
    asm volatile("st.shared.u16 [%0], %1;" :: "r"(a), "h"(v));
}
__device__ __forceinline__ ull lds_u64(uint32_t a) {
    ull v; asm volatile("ld.shared.b64 %0, [%1];" : "=l"(v) : "r"(a)); return v;
}
__device__ __forceinline__ void sts_u64(uint32_t a, ull v) {
    asm volatile("st.shared.b64 [%0], %1;" :: "r"(a), "l"(v));
}

// H tile: [n row] x [k (0..511)] bf16, 1024 B rows, XOR-swizzled
__device__ __forceinline__ uint32_t h_addr(uint32_t hb, int n, int k) {
    return hb + n * 1024 + ((((k >> 3) ^ (n & 7)) << 4) | ((k & 7) << 1));
}
// D (fp32) overlay in H region: [n][o], XOR-swizzled
__device__ __forceinline__ uint32_t d_addr(uint32_t hb, int n, int o) {
    return hb + n * 1024 + ((o ^ ((n & 7) << 2)) << 2);
}

__device__ __forceinline__ void split2(float v, uint16_t& hi, uint16_t& lo) {
    __nv_bfloat16 h = __float2bfloat16(v);
    __nv_bfloat16 l = __float2bfloat16(v - __bfloat162float(h));
    hi = __bfloat16_as_ushort(h);
    lo = __bfloat16_as_ushort(l);
}

// ---------------------------------------------------------------------------
// device globals + merged prep kernel
// g_wf: W in MMA-fragment-major layout: [lp = layer*2+part][mtile][ktile][lane]
//   each uint4 = the 4 a-regs of m16n8k16 for that lane (row-major W tile).
// ---------------------------------------------------------------------------
__device__ float g_pe[PE_LEN * CDIM];
__device__ uint4 g_wf[6 * 16 * 16 * 32];            // 768 KB, L2-resident

#define PE_N   (PE_LEN * CDIM)                      // 22784
#define WF_N   (6 * 16 * 16 * 32)                   // 49152

__global__ void prep_kernel(const float* __restrict__ w1,
                            const float* __restrict__ w2,
                            const float* __restrict__ wp) {
    int idx = blockIdx.x * blockDim.x + threadIdx.x;
    if (idx < PE_N) {
        int row = idx / CDIM, c = idx % CDIM;
        int p2 = (c >> 1) * 2;
        float divf = expf((float)p2 * (-9.210340371976184f / 256.0f));
        double ang = (double)row * (double)divf;
        g_pe[idx] = (c & 1) ? (float)cos(ang) : (float)sin(ang);
    } else if (idx < PE_N + WF_N) {
        int t = idx - PE_N;
        int lane = t & 31, kt = (t >> 5) & 15, mt = (t >> 9) & 15, lp = t >> 13;
        int l = lp >> 1, part = lp & 1;
        const float* w = (l == 0) ? w1 : ((l == 1) ? w2 : wp);
        int r = lane >> 2, c0 = (lane & 3) * 2;
        uint32_t q[4];
#pragma unroll
        for (int m = 0; m < 4; m++) {
            int row = mt * 16 + r + ((m & 1) << 3);
            int col = kt * 16 + c0 + ((m >> 1) << 3);
            uint16_t h0, l0, h1, l1;
            split2(w[row * 256 + col], h0, l0);
            split2(w[row * 256 + col + 1], h1, l1);
            uint16_t e0 = part ? l0 : h0, e1 = part ? l1 : h1;
            q[m] = (uint32_t)e0 | ((uint32_t)e1 << 16);
        }
        g_wf[t] = make_uint4(q[0], q[1], q[2], q[3]);
    }
}

// fragment fetch: one LDG.128 per m-tile per k-tile (warp-coalesced 512B)
__device__ __forceinline__ void load_a(uint4* dst, int s, int wid, int lane) {
    const uint4* wf = g_wf + (size_t)(s >> 4) * 8192 + (size_t)(s & 15) * 32
                    + lane;
    dst[0] = __ldg(wf + (size_t)(wid * 2) * 512);
    dst[1] = __ldg(wf + (size_t)(wid * 2 + 1) * 512);
}

// ---------------------------------------------------------------------------
// main kernel: 1 CTA = 2 samples (rows n = s*25+v); 256 threads = 8 warps,
// warp tile 32(o) x 56(rows); GEMM loop has ZERO barriers (W via direct LDG
// from L2-hot fragment-major table, H ldsm from SMEM); 2 CTAs/SM
// ---------------------------------------------------------------------------
__global__ void __launch_bounds__(NTHR, 2)
ode_main(const float* __restrict__ x, const float* __restrict__ A,
         const float* __restrict__ b1, const float* __restrict__ b2,
         const float* __restrict__ bp, const int* __restrict__ tptr,
         float* __restrict__ out) {
    extern __shared__ char raw[];
    uint32_t rawu = smem_u32(raw);
    uint32_t base = (rawu + 1023u) & ~1023u;

    const int tid = threadIdx.x, lane = tid & 31, wid = tid >> 5;
    const int blk = blockIdx.x;
    const uint32_t hb = base + H_OFF;
    const int ob = wid * 32;            // warp m-tile origin (o), 8 warps

    // stage A (packed f32x2 rows) + biases
    for (int i = tid; i < VDIM * 13; i += NTHR) {
        int v = i / 13, j = i % 13, u0 = 2 * j, u1 = 2 * j + 1;
        float f0 = A[v * VDIM + u0];
        float f1 = (u1 < VDIM) ? A[v * VDIM + u1] : 0.f;
        ull p = (ull)__float_as_uint(f0) | ((ull)__float_as_uint(f1) << 32);
        sts_u64(base + AS2_OFF + i * 8, p);
    }
    for (int i = tid; i < 768; i += NTHR) {
        float bv = (i < 256) ? b1[i] : ((i < 512) ? b2[i - 256] : bp[i - 512]);
        sts_f32(base + BIAS_OFF + i * 4, bv);
    }

    // build H = split(x + pe): rows n = s*25+v
    const int t0 = *tptr;
    for (int i = tid; i < NSAMP * CDIM * VDIM; i += NTHR) {
        int s = i / (CDIM * VDIM);
        int rem = i - s * (CDIM * VDIM);
        int c = rem / VDIM, v = rem - c * VDIM;
        int n = blk * NSAMP + s;
        float val = x[(size_t)n * (CDIM * VDIM) + rem]
                  + g_pe[(t0 + (n & 63)) * CDIM + c];
        uint16_t hi, lo;
        split2(val, hi, lo);
        int nr = s * VDIM + v;
        sts_u16(h_addr(hb, nr, c), hi);
        sts_u16(h_addr(hb, nr, 256 + c), lo);
    }
    __syncthreads();

    float acc[2][7][4];
#pragma unroll
    for (int i = 0; i < 2; i++)
#pragma unroll
        for (int j = 0; j < 7; j++)
#pragma unroll
            for (int e = 0; e < 4; e++) acc[i][j][e] = 0.f;

    // 96 steps: 3 layers x {part0(Wh): kt 0..15, part1(Wl): kt 0..15}
    uint4 a0[2], a1[2];
    load_a(a0, 0, wid, lane);
    load_a(a1, 1, wid, lane);

#pragma unroll 2
    for (int s = 0; s < 96; s++) {
        const int part = (s >> 4) & 1;
        const int kt = s & 15;

#pragma unroll
        for (int tgt = 0; tgt < 2; tgt++) {
            if (part && tgt) break;                  // Wl: Hh only
            int kh = (part ? 0 : tgt * 256) + kt * 16;
            uint32_t b[8][2];
            {
                int sel = lane >> 3;
                int n0 = (lane & 7) + ((sel >> 1) << 3);
                int k = kh + ((sel & 1) << 3);
#pragma unroll
                for (int jj = 0; jj < 4; jj++) {
                    uint32_t r[4];
                    ldsm4(r, h_addr(hb, n0 + jj * 16, k));
                    b[2 * jj][0] = r[0]; b[2 * jj][1] = r[1];
                    b[2 * jj + 1][0] = r[2]; b[2 * jj + 1][1] = r[3];
                }
            }
#pragma unroll
            for (int i = 0; i < 2; i++)
#pragma unroll
                for (int j = 0; j < 7; j++)
                    mma_bf16(acc[i][j], (const uint32_t*)&a0[i], b[j]);
        }

        // rotate prefetch pipeline (2-deep)
        a0[0] = a1[0]; a0[1] = a1[1];
        int sn = (s + 2 < 96) ? s + 2 : 95;
        load_a(a1, sn, wid, lane);

        if ((s & 31) == 31) {            // ---- layer epilogue ----
            const int l = s >> 5;
            if (l < 2) {
                __syncthreads();         // all warps done reading H this layer
                // 1) acc -> D (fp32 overlay on H region), real rows only
#pragma unroll
                for (int i = 0; i < 2; i++) {
                    int o = ob + i * 16 + (lane >> 2);
#pragma unroll
                    for (int j = 0; j < 7; j++) {
                        int n = j * 8 + 2 * (lane & 3);
                        if (n < 50) {
                            sts_f32(d_addr(hb, n, o),     acc[i][j][0]);
                            sts_f32(d_addr(hb, n, o + 8), acc[i][j][2]);
                        }
                        if (n + 1 < 50) {
                            sts_f32(d_addr(hb, n + 1, o),     acc[i][j][1]);
                            sts_f32(d_addr(hb, n + 1, o + 8), acc[i][j][3]);
                        }
                    }
                }
                __syncthreads();
                // 2) channel o = tid; both samples' D rows into regs
                const int o = tid;
                ull du[NSAMP][13];
#pragma unroll
                for (int sm = 0; sm < NSAMP; sm++) {
                    float tv[26];
                    tv[25] = 0.f;
#pragma unroll
                    for (int u = 0; u < 25; u++)
                        tv[u] = lds_f32(d_addr(hb, sm * VDIM + u, o));
#pragma unroll
                    for (int j = 0; j < 13; j++)
                        du[sm][j] = (ull)__float_as_uint(tv[2 * j])
                                  | ((ull)__float_as_uint(tv[2 * j + 1]) << 32);
                }
                __syncthreads();
                // 3) A^T mult + bias + lrelu + re-split into H (v-outer)
                float bb = lds_f32(base + BIAS_OFF + (l * 256 + o) * 4);
#pragma unroll 5
                for (int v = 0; v < VDIM; v++) {
                    ull ar[13];
#pragma unroll
                    for (int j = 0; j < 13; j++)
                        ar[j] = lds_u64(base + AS2_OFF + (v * 13 + j) * 8);
#pragma unroll
                    for (int sm = 0; sm < NSAMP; sm++) {
                        ull accv = 0ull;
#pragma unroll
                        for (int j = 0; j < 13; j++)
                            accv = fma2(du[sm][j], ar[j], accv);
                        float a_0, a_1;
                        asm("mov.b64 {%0,%1}, %2;"
                            : "=f"(a_0), "=f"(a_1) : "l"(accv));
                        float rr = a_0 + a_1 + bb;
                        rr = (rr >= 0.f) ? rr : NEG_SLOPE * rr;
                        uint16_t hi, lo;
                        split2(rr, hi, lo);
                        int nr = sm * VDIM + v;
                        sts_u16(h_addr(hb, nr, o), hi);
                        sts_u16(h_addr(hb, nr, 256 + o), lo);
                    }
                }
                __syncthreads();
            } else {
                // final layer: bias + direct gmem store from fragments
#pragma unroll
                for (int i = 0; i < 2; i++) {
                    int o0 = ob + i * 16 + (lane >> 2);
                    float bb0 = lds_f32(base + BIAS_OFF + (512 + o0) * 4);
                    float bb1 = lds_f32(base + BIAS_OFF + (512 + o0 + 8) * 4);
#pragma unroll
                    for (int j = 0; j < 7; j++) {
                        int n = j * 8 + 2 * (lane & 3);
#pragma unroll
                        for (int e = 0; e < 2; e++) {
                            int r = n + e;
                            if (r < NSAMP * VDIM) {
                                int sm = (r >= VDIM) ? 1 : 0;
                                int v = r - sm * VDIM;
                                size_t o_base =
                                    ((size_t)(blk * NSAMP + sm)) * (CDIM * VDIM);
                                out[o_base + o0 * VDIM + v]
                                    = acc[i][j][e] + bb0;
                                out[o_base + (o0 + 8) * VDIM + v]
                                    = acc[i][j][e + 2] + bb1;
                            }
                        }
                    }
                }
            }
            // reset accumulators for next layer
#pragma unroll
            for (int i = 0; i < 2; i++)
#pragma unroll
                for (int j = 0; j < 7; j++)
#pragma unroll
                    for (int e = 0; e < 4; e++) acc[i][j][e] = 0.f;
        }
    }
}

// ---------------------------------------------------------------------------
extern "C" void kernel_launch(void* const* d_in, const int* in_sizes, int n_in,
                              void* d_out, int out_size) {
    const float* x  = (const float*)d_in[0];
    const float* A  = (const float*)d_in[1];
    const float* w1 = (const float*)d_in[2];
    const float* b1 = (const float*)d_in[3];
    const float* w2 = (const float*)d_in[4];
    const float* b2 = (const float*)d_in[5];
    const float* wp = (const float*)d_in[6];
    const float* bp = (const float*)d_in[7];
    const int*   t  = (const int*)d_in[8];
    float* out = (float*)d_out;

    const int B = in_sizes[0] / (CDIM * VDIM);   // 4096

    cudaFuncSetAttribute(ode_main, cudaFuncAttributeMaxDynamicSharedMemorySize,
                         SMEM_DYN);

    prep_kernel<<<(PE_N + WF_N + 255) / 256, 256>>>(w1, w2, wp);
    ode_main<<<B / NSAMP, NTHR, SMEM_DYN>>>(x, A, b1, b2, bp, t, out);
}